// round 17
// baseline (speedup 1.0000x reference)
#include <cuda_runtime.h>
#include <cuda_bf16.h>

// CTC forward, LINEAR domain, per-thread exponent scaling, WARP-SPECIALIZED,
// TWO skewed consumer warps + two producer warps (128 threads / batch elem).
//   warp 0: lattice pairs 0..63   (2 pairs/lane, packed f32x2), chunk c at phase c+1
//   warp 1: lattice pairs 64..127 (+ state 2L), chunk c at phase c+2 (one chunk behind)
//   warps 2,3: producers -> emission ratios into a TRIPLE-buffered smem ring.
// Cross-warp boundary O_63(t): warp 0 publishes (exponent, value) u64 per step
// into a 96-slot array (3-chunk lifetime; every hand-off barrier-separated);
// warp 1 rescales by the exact power-of-2 exponent difference.
// Renorm: per-thread, measure j%4==1 / apply j%4==3 (proven safe cadence).

#define LOG2E 1.4426950408889634f
#define LN2   0.6931471805599453f
#define FULLM 0xffffffffu
#define MAXB  4096
#define CH    32
#define PSH   16
#define NBND  96

__device__ float        g_per_ex[MAXB];
__device__ unsigned int g_count = 0;

typedef unsigned long long u64;

__device__ __forceinline__ float ex2f_(float x){ float r; asm("ex2.approx.f32 %0,%1;" : "=f"(r) : "f"(x)); return r; }
__device__ __forceinline__ float lg2f_(float x){ float r; asm("lg2.approx.f32 %0,%1;" : "=f"(r) : "f"(x)); return r; }

__device__ __forceinline__ u64  PK2(float lo, float hi){ u64 r; asm("mov.b64 %0,{%1,%2};" : "=l"(r) : "f"(lo), "f"(hi)); return r; }
__device__ __forceinline__ void UPK(u64 v, float& lo, float& hi){ asm("mov.b64 {%0,%1},%2;" : "=f"(lo), "=f"(hi) : "l"(v)); }
__device__ __forceinline__ u64  ADD2(u64 a, u64 b){ u64 r; asm("add.rn.f32x2 %0,%1,%2;" : "=l"(r) : "l"(a), "l"(b)); return r; }
__device__ __forceinline__ u64  MUL2(u64 a, u64 b){ u64 r; asm("mul.rn.f32x2 %0,%1,%2;" : "=l"(r) : "l"(a), "l"(b)); return r; }
__device__ __forceinline__ u64  FMA2(u64 a, u64 b, u64 c){ u64 r; asm("fma.rn.f32x2 %0,%1,%2,%3;" : "=l"(r) : "l"(a), "l"(b), "l"(c)); return r; }

__global__ __launch_bounds__(128, 1)
void ctc_forward_kernel(const float* __restrict__ pred,           // (B, T, C)
                        const int*   __restrict__ targets,        // (B, L)
                        const int*   __restrict__ pred_lengths,   // (B,)
                        const int*   __restrict__ target_lengths, // (B,)
                        float*       __restrict__ out,
                        int T, int C, int L, int B)
{
    extern __shared__ float ringF[];     // [3][CH][128] floats = 48 KB dynamic
    __shared__ u64   bnd[NBND];          // boundary (e<<32 | O_63 bits), 3-chunk life
    __shared__ float sE[129];
    __shared__ float sO[128];
    __shared__ int   sExp[64];
    __shared__ float s_eb[2];
    __shared__ unsigned int s_last;

    const int b   = blockIdx.x;
    const int tid = threadIdx.x;
    const int wid = tid >> 5;            // 0,1 consumers; 2,3 producers
    const int wl  = tid & 31;

    const float* rowp = pred + (size_t)b * T * C;
    int pl = pred_lengths[b];
    int Teff = pl < T ? pl : T; if (Teff < 1) Teff = 1;
    const int steps = Teff - 1;          // updates at t = 1..steps
    const int fc    = steps / CH;
    const int rem   = steps - fc * CH;
    const int nchAll = fc + (rem ? 1 : 0);

    if (tid == 0) bnd[0] = 0ull;         // O_63(t=0) = 0, exponent 0

    // =================== consumer state (warps 0,1) ===================
    const int W  = wid;                  // valid only for wid<2
    const int pA = (wid < 2) ? (W * 64 + 2 * wl) : 0;
    u64 SKa = 0;
    float exm = 0.f;
    u64 Oa = 0, Ea = 0; float EX = 0.f;
    int   e_i = 0;
    float sc_intra = (wl == 0) ? 0.f : 1.f;
    float rn_sc = 1.f; int rn_ee = 0;
    if (wid < 2) {
        int liA = pA     < L ? pA     : L - 1;
        int liB = pA + 1 < L ? pA + 1 : L - 1;
        int lA  = targets[(size_t)b * L + liA];
        int lAp = (liA >= 1) ? targets[(size_t)b * L + liA - 1] : -1;
        int lB  = targets[(size_t)b * L + liB];
        int lBp = (liB >= 1) ? targets[(size_t)b * L + liB - 1] : -1;
        float skA = (lA != 0 && lA != lAp) ? 1.f : 0.f;
        float skB = (lB != 0 && lB != lBp) ? 1.f : 0.f;
        SKa = PK2(skA, skB);
        exm = (W == 1 && wl == 31) ? 1.f : 0.f;
        if (W == 0 && wl == 0) {
            float eb0 = __ldg(rowp) * LOG2E;
            float o0  = ex2f_(fmaf(__ldg(rowp + lA), LOG2E, -eb0));
            Ea = PK2(1.f, 0.f);
            Oa = PK2(o0, 0.f);
        }
    }

#define MEASURE()                                                            \
    {                                                                        \
        float o0_, o1_, e0_, e1_;                                            \
        UPK(Oa, o0_, o1_); UPK(Ea, e0_, e1_);                                \
        float m = fmaxf(fmaxf(o0_, o1_), fmaxf(e0_, e1_));                   \
        m = fmaxf(m, EX * exm);                                              \
        rn_ee = 0;                                                           \
        if (m > 0.f) rn_ee = (int)((__float_as_uint(m) >> 23) & 0xffu) - 127;\
        rn_sc = __uint_as_float((unsigned)(127 - rn_ee) << 23);              \
    }
#define APPLY()                                                              \
    {                                                                        \
        u64 SC = PK2(rn_sc, rn_sc);                                          \
        Oa = MUL2(Oa, SC); Ea = MUL2(Ea, SC);                                \
        EX *= rn_sc;                                                         \
        e_i += rn_ee;                                                        \
        int ep = __shfl_up_sync(FULLM, e_i, 1);                              \
        int de2 = ep - e_i;                                                  \
        de2 = de2 > 126 ? 126 : (de2 < -126 ? -126 : de2);                   \
        sc_intra = (wl == 0) ? 0.f                                           \
                 : __uint_as_float((unsigned)(127 + de2) << 23);             \
    }

    // warp 0 step: publish boundary (value, exponent) after update
#define W0STEP(RB, J, SB0)                                                   \
    {                                                                        \
        float2 r = *(const float2*)((RB) + (J) * 128);                       \
        float o0_, o1_; UPK(Oa, o0_, o1_);                                   \
        float sh  = __shfl_up_sync(FULLM, o1_, 1);                           \
        float Om1 = sh * sc_intra;                                           \
        u64 Sa = PK2(Om1, o0_);                                              \
        u64 Ra = PK2(r.x, r.y);                                              \
        u64 ta = ADD2(Oa, Ea);                                               \
        Oa = MUL2(FMA2(SKa, Sa, ta), Ra);                                    \
        Ea = ADD2(Ea, Sa);                                                   \
        if (wl == 31) {                                                      \
            float n0_, n1_; UPK(Oa, n0_, n1_); (void)n0_;                    \
            int sl = (SB0) + (J); if (sl >= NBND) sl -= NBND;                \
            bnd[sl] = ((u64)(unsigned)e_i << 32)                             \
                    | (u64)__float_as_uint(n1_);                             \
        }                                                                    \
    }

    // warp 1 step: cross-boundary value with exact power-of-2 rescale
#define W1STEP(RB, J, BASE3, NFULL)                                          \
    {                                                                        \
        float2 r = *(const float2*)((RB) + (J) * 128);                       \
        float o0_, o1_; UPK(Oa, o0_, o1_);                                   \
        float sh = __shfl_up_sync(FULLM, o1_, 1);                            \
        u64 pk = pf[(J) & 3];                                                \
        float bv = __uint_as_float((unsigned)pk);                            \
        int be = (int)(unsigned)(pk >> 32);                                  \
        int de = be - e_i;                                                   \
        de = de > 126 ? 126 : (de < -126 ? -126 : de);                       \
        float cross = bv * __uint_as_float((unsigned)(127 + de) << 23);      \
        float Om1 = (wl == 0) ? cross : sh * sc_intra;                       \
        u64 Sa = PK2(Om1, o0_);                                              \
        u64 Ra = PK2(r.x, r.y);                                              \
        u64 ta = ADD2(Oa, Ea);                                               \
        Oa = MUL2(FMA2(SKa, Sa, ta), Ra);                                    \
        Ea = ADD2(Ea, Sa);                                                   \
        EX += o1_;                                                           \
        if ((J) + 4 < (NFULL)) {                                             \
            int sl2 = (BASE3) + (J) + 4; if (sl2 >= NBND) sl2 -= NBND;       \
            pf[(J) & 3] = bnd[sl2];                                          \
        }                                                                    \
    }

    // =================== producer state (warps 2,3) ===================
    int   cols[4]; float vm[4];
    float rb_[PSH], r0_[PSH], r1_[PSH], r2_[PSH], r3_[PSH];
    float pebs = 0.f;
    const int pw = wid - 2;
    if (wid >= 2) {
#pragma unroll
        for (int k = 0; k < 4; k++) {
            int p  = wl * 4 + k;
            int li = (p < L) ? p : (L - 1);
            cols[k] = targets[(size_t)b * L + li];
            vm[k]   = (p < L) ? 1.f : 0.f;
        }
        if (pw == 0) pebs = __ldg(rowp) * LOG2E;       // t = 0 blank term
#pragma unroll
        for (int jj = 0; jj < PSH; jj++) {
            int tt = pw * PSH + jj + 1;
            int tc = tt > steps ? steps : tt;
            const float* pp = rowp + (size_t)tc * C;
            rb_[jj] = __ldg(pp);
            r0_[jj] = __ldg(pp + cols[0]);
            r1_[jj] = __ldg(pp + cols[1]);
            r2_[jj] = __ldg(pp + cols[2]);
            r3_[jj] = __ldg(pp + cols[3]);
        }
    }

    u64 pf[4];                            // warp-1 boundary prefetch ring

    // =================== phase loop ===================
    for (int p = 0; p <= nchAll + 1; p++) {
        if (wid >= 2) {
            if (p < nchAll) {
                const int buf = p % 3;
                float* wbase = ringF + (size_t)(buf * CH) * 128 + wl * 4;
#pragma unroll
                for (int jj = 0; jj < PSH; jj++) {
                    const int j = pw * PSH + jj;
                    const int tglob = p * CH + j + 1;
                    float ebv = rb_[jj] * LOG2E;
                    float4 o;
                    o.x = ex2f_(fmaf(r0_[jj], LOG2E, -ebv)) * vm[0];
                    o.y = ex2f_(fmaf(r1_[jj], LOG2E, -ebv)) * vm[1];
                    o.z = ex2f_(fmaf(r2_[jj], LOG2E, -ebv)) * vm[2];
                    o.w = ex2f_(fmaf(r3_[jj], LOG2E, -ebv)) * vm[3];
                    *(float4*)(wbase + (size_t)j * 128) = o;
                    if (tglob <= steps) pebs += ebv;
                }
#pragma unroll
                for (int jj = 0; jj < PSH; jj++) {
                    int tn = (p + 1) * CH + pw * PSH + jj + 1;
                    if (tn > steps) tn = steps;
                    const float* pp = rowp + (size_t)tn * C;
                    rb_[jj] = __ldg(pp);
                    r0_[jj] = __ldg(pp + cols[0]);
                    r1_[jj] = __ldg(pp + cols[1]);
                    r2_[jj] = __ldg(pp + cols[2]);
                    r3_[jj] = __ldg(pp + cols[3]);
                }
            }
        } else if (W == 0) {
            if (p >= 1 && p <= nchAll) {
                const int cidx = p - 1;
                const int buf  = cidx % 3;
                const int sb0  = (cidx % 3) * CH + 1;   // slot of t = cidx*CH+1
                const float* rb0 = ringF + (size_t)(buf * CH) * 128 + 2 * wl;
                if (cidx < fc) {
#pragma unroll
                    for (int j = 0; j < CH; j++) {
                        W0STEP(rb0, j, sb0);
                        if ((j & 3) == 1) MEASURE();
                        if ((j & 3) == 3) APPLY();
                    }
                } else {
                    for (int j = 0; j < rem; j++) {
                        W0STEP(rb0, j, sb0);
                        if ((j & 3) == 1) MEASURE();
                        if ((j & 3) == 3) APPLY();
                    }
                }
            }
        } else { // W == 1
            if (p >= 2 && p <= nchAll + 1) {
                const int cidx  = p - 2;
                const int buf   = cidx % 3;
                const int base3 = (cidx % 3) * CH;      // slot of t = cidx*CH
                const float* rb1 = ringF + (size_t)(buf * CH) * 128 + 64 + 2 * wl;
#pragma unroll
                for (int k = 0; k < 4; k++) pf[k] = bnd[base3 + k];
                if (cidx < fc) {
#pragma unroll
                    for (int j = 0; j < CH; j++) {
                        W1STEP(rb1, j, base3, CH);
                        if ((j & 3) == 1) MEASURE();
                        if ((j & 3) == 3) APPLY();
                    }
                } else {
                    for (int j = 0; j < rem; j++) {
                        W1STEP(rb1, j, base3, rem);
                        if ((j & 3) == 1) MEASURE();
                        if ((j & 3) == 3) APPLY();
                    }
                }
            }
        }
        __syncthreads();
    }
#undef W0STEP
#undef W1STEP
#undef MEASURE
#undef APPLY

    // =================== gather + per-example loss ===================
    if (wid < 2) {
        float o0_, o1_, e0_, e1_;
        UPK(Oa, o0_, o1_); UPK(Ea, e0_, e1_);
        sO[pA] = o0_; sO[pA + 1] = o1_;
        sE[pA] = e0_; sE[pA + 1] = e1_;
        if (W == 1 && wl == 31) sE[128] = EX;
        sExp[W * 32 + wl] = e_i;
    } else if (wl == 0) {
        s_eb[pw] = pebs;
    }
    __syncthreads();

    if (tid == 0) {
        float ebsum = s_eb[0] + s_eb[1];
        int tl = target_lengths[b];
        int tlc = tl; if (tlc < 1) tlc = 1; if (tlc > L) tlc = L;
        float l1v = sO[tlc - 1];                       // state 2*tl - 1
        int   e1x = sExp[(tlc - 1) >> 1];
        float l2v = sE[tlc];                           // state 2*tl
        int   e2x = (tlc < 128) ? sExp[tlc >> 1] : sExp[63];
        float g1 = lg2f_(l1v) + (float)e1x;
        float g2 = lg2f_(l2v) + (float)e2x;
        float mm = fmaxf(g1, g2);
        float dd = fminf(g1, g2) - mm;
        float logv = mm + lg2f_(1.f + ex2f_(dd)) + ebsum;   // log2 P
        float per = -LN2 * logv;
        if (!(per < 1e29f)) per = 0.f;                 // zero_infinity (+inf/NaN)
        int den = tl < 1 ? 1 : tl;
        g_per_ex[b] = per / (float)den;
        __threadfence();
        unsigned pc = atomicAdd(&g_count, 1u);
        s_last = (pc == (unsigned)(B - 1)) ? 1u : 0u;
    }
    __syncthreads();

    // ---- last block computes the batch mean (deterministic fixed order) ----
    if (s_last && wid == 0) {
        float v = 0.f;
        for (int idx = wl; idx < B; idx += 32)
            v += *((volatile float*)&g_per_ex[idx]);
#pragma unroll
        for (int o = 16; o > 0; o >>= 1)
            v += __shfl_down_sync(FULLM, v, o);
        if (wl == 0) { out[0] = v / (float)B; g_count = 0u; }
    }
}

extern "C" void kernel_launch(void* const* d_in, const int* in_sizes, int n_in,
                              void* d_out, int out_size)
{
    const float* pred           = (const float*)d_in[0];
    const int*   targets        = (const int*)d_in[1];
    const int*   pred_lengths   = (const int*)d_in[2];
    const int*   target_lengths = (const int*)d_in[3];

    const int B = in_sizes[2];
    const int L = in_sizes[1] / B;
    const int C = 128;
    const int T = (in_sizes[0] / B) / C;

    const int ringBytes = 3 * CH * 128 * (int)sizeof(float);   // 48 KB
    cudaFuncSetAttribute(ctc_forward_kernel,
                         cudaFuncAttributeMaxDynamicSharedMemorySize, ringBytes);

    ctc_forward_kernel<<<B, 128, ringBytes>>>(pred, targets, pred_lengths,
                                              target_lengths, (float*)d_out,
                                              T, C, L, B);
}